// round 3
// baseline (speedup 1.0000x reference)
#include <cuda_runtime.h>
#include <cstdint>

// Problem constants (fixed by reference): B=64, MEL_MAX=2000, TEXT_MAX=256
#define BATCH   64
#define MEL_MAX 2000
#define TXT_MAX 256
#define G_FACTOR 0.2f
// 1 / (2*g^2) = 1 / 0.08 = 12.5
#define INV_2G2 12.5f

#define NROWS (BATCH * MEL_MAX)          // 128000
#define RED_BLOCKS (NROWS / 1024)        // 125 (exact: 128000 = 125*1024)

// Scratch: __device__ globals (no allocation allowed)
__device__ float  g_part[NROWS];
__device__ double g_part2[RED_BLOCKS];

// ---------------------------------------------------------------------------
// Kernel 1: one block per (b, t) row. 256 threads, one text position each.
// Writes one float partial per row (0 for invalid rows).
// ---------------------------------------------------------------------------
__global__ __launch_bounds__(TXT_MAX) void row_kernel(
    const float* __restrict__ pred,
    const int*   __restrict__ tlen,
    const int*   __restrict__ mlen)
{
    const int row = blockIdx.x;
    const int b   = row / MEL_MAX;
    const int t   = row - b * MEL_MAX;

    const int ml = __ldg(&mlen[b]);

    float v = 0.0f;
    if (t < ml) {
        const int tl = __ldg(&tlen[b]);
        const int n  = threadIdx.x;
        if (n < tl) {
            const float p = __ldg(&pred[(size_t)row * TXT_MAX + n]);
            const float inv_tl = 1.0f / (float)tl;
            const float inv_ml = 1.0f / (float)ml;
            const float d = (float)n * inv_tl - (float)t * inv_ml;
            const float guide = 1.0f - __expf(-(d * d) * INV_2G2);
            v = guide * p;
        }
    }

    // Block reduction: 8 warps of 32
    #pragma unroll
    for (int o = 16; o > 0; o >>= 1)
        v += __shfl_xor_sync(0xFFFFFFFFu, v, o);

    __shared__ float ws[8];
    const int lane = threadIdx.x & 31;
    const int wid  = threadIdx.x >> 5;
    if (lane == 0) ws[wid] = v;
    __syncthreads();

    if (threadIdx.x < 8) {
        v = ws[threadIdx.x];
        #pragma unroll
        for (int o = 4; o > 0; o >>= 1)
            v += __shfl_xor_sync(0x000000FFu, v, o);
        if (threadIdx.x == 0)
            g_part[row] = v;
    }
}

// ---------------------------------------------------------------------------
// Kernel 2: 125 blocks x 1024 threads, each block reduces 1024 partials
// in double precision (deterministic, no atomics).
// ---------------------------------------------------------------------------
__global__ __launch_bounds__(1024) void reduce_kernel()
{
    const int idx = blockIdx.x * 1024 + threadIdx.x;
    double v = (double)g_part[idx];

    #pragma unroll
    for (int o = 16; o > 0; o >>= 1)
        v += __shfl_xor_sync(0xFFFFFFFFu, v, o);

    __shared__ double ws[32];
    const int lane = threadIdx.x & 31;
    const int wid  = threadIdx.x >> 5;
    if (lane == 0) ws[wid] = v;
    __syncthreads();

    if (threadIdx.x < 32) {
        v = ws[threadIdx.x];
        #pragma unroll
        for (int o = 16; o > 0; o >>= 1)
            v += __shfl_xor_sync(0xFFFFFFFFu, v, o);
        if (threadIdx.x == 0)
            g_part2[blockIdx.x] = v;
    }
}

// ---------------------------------------------------------------------------
// Kernel 3: single block of 128 threads. Sums the 125 block partials and
// computes active = sum(tl*ml) on-device, writes final scalar.
// ---------------------------------------------------------------------------
__global__ __launch_bounds__(128) void final_kernel(
    const int* __restrict__ tlen,
    const int* __restrict__ mlen,
    float* __restrict__ out)
{
    const int i = threadIdx.x;
    double v = (i < RED_BLOCKS) ? g_part2[i] : 0.0;
    double a = (i < BATCH) ? (double)tlen[i] * (double)mlen[i] : 0.0;

    #pragma unroll
    for (int o = 16; o > 0; o >>= 1) {
        v += __shfl_xor_sync(0xFFFFFFFFu, v, o);
        a += __shfl_xor_sync(0xFFFFFFFFu, a, o);
    }

    __shared__ double sv[4], sa[4];
    const int lane = i & 31;
    const int wid  = i >> 5;
    if (lane == 0) { sv[wid] = v; sa[wid] = a; }
    __syncthreads();

    if (i == 0) {
        double tv = sv[0] + sv[1] + sv[2] + sv[3];
        double ta = sa[0] + sa[1] + sa[2] + sa[3];
        // attention_weight = 1.0
        out[0] = (float)(tv / ta);
    }
}

// ---------------------------------------------------------------------------
// Launch: inputs per metadata order: targets (unused), predictions,
// text_lengths, mel_lengths. Output: single float.
// ---------------------------------------------------------------------------
extern "C" void kernel_launch(void* const* d_in, const int* in_sizes, int n_in,
                              void* d_out, int out_size)
{
    (void)in_sizes; (void)n_in; (void)out_size;
    const float* pred = (const float*)d_in[1];
    const int*   tlen = (const int*)d_in[2];
    const int*   mlen = (const int*)d_in[3];
    float*       out  = (float*)d_out;

    row_kernel<<<NROWS, TXT_MAX>>>(pred, tlen, mlen);
    reduce_kernel<<<RED_BLOCKS, 1024>>>();
    final_kernel<<<1, 128>>>(tlen, mlen, out);
}

// round 4
// speedup vs baseline: 3.5814x; 3.5814x over previous
#include <cuda_runtime.h>
#include <cstdint>

// Problem constants (fixed by reference): B=64, MEL_MAX=2000, TEXT_MAX=256
#define BATCH   64
#define MEL_MAX 2000
#define TXT_MAX 256
// 1 / (2*g^2) with g=0.2  ->  12.5
#define A_COEF  12.5f

#define NROWS   (BATCH * MEL_MAX)        // 128000
#define NBLK    888                      // 148 SMs * 6 CTAs
#define NTHR    256                      // 8 warps per CTA

// Scratch (__device__ globals — no allocation allowed)
__device__ double g_block[NBLK];

// ---------------------------------------------------------------------------
// Kernel 1: persistent warp-per-row. Each lane owns 8 contiguous text
// positions (n = 8*lane .. 8*lane+7); 32 lanes cover TEXT_MAX=256 exactly.
// Gaussian computed by multiplicative recurrence: 3 MUFU per 8 elements.
// ---------------------------------------------------------------------------
__global__ __launch_bounds__(NTHR) void row_kernel(
    const float* __restrict__ pred,
    const int*   __restrict__ tlen,
    const int*   __restrict__ mlen)
{
    const int lane    = threadIdx.x & 31;
    const int wid     = threadIdx.x >> 5;
    const int gwarp   = blockIdx.x * 8 + wid;
    const int nwarps  = NBLK * 8;

    const int n0 = lane * 8;

    float tsp  = 0.0f;   // sum of p over valid elems
    float tsep = 0.0f;   // sum of E*p over valid elems

    for (int row = gwarp; row < NROWS; row += nwarps) {
        const int b = row / MEL_MAX;
        const int t = row - b * MEL_MAX;

        const int ml = __ldg(&mlen[b]);
        if (t >= ml) continue;
        const int tl = __ldg(&tlen[b]);

        int count = tl - n0;               // valid elements in this lane's chunk
        if (count <= 0) continue;
        if (count > 8) count = 8;

        const float inv_tl = 1.0f / (float)tl;
        const float inv_ml = 1.0f / (float)ml;
        const float beta   = (float)t * inv_ml;

        // E(n)   = exp(-A (n*inv_tl - beta)^2)
        // m(n)   = E(n+1)/E(n) = exp(-A*inv_tl^2*(2n+1) + 2A*inv_tl*beta)
        // q2     = m(n+1)/m(n) = exp(-2A*inv_tl^2)
        const float d0 = (float)n0 * inv_tl - beta;
        float E  = __expf(-A_COEF * d0 * d0);
        float m  = __expf(inv_tl * (2.0f * A_COEF * beta
                          - A_COEF * inv_tl * (float)(2 * n0 + 1)));
        const float q2 = __expf(-2.0f * A_COEF * inv_tl * inv_tl);

        // Two float4 loads: n0 .. n0+7 (always in-bounds: n0 <= 248)
        const float4* rp = (const float4*)(pred + (size_t)row * TXT_MAX + n0);
        const float4 v0 = __ldg(rp);
        const float4 v1 = __ldg(rp + 1);
        float vals[8] = {v0.x, v0.y, v0.z, v0.w, v1.x, v1.y, v1.z, v1.w};

        #pragma unroll
        for (int j = 0; j < 8; j++) {
            const float pj = (j < count) ? vals[j] : 0.0f;
            tsp  += pj;
            tsep  = fmaf(E, pj, tsep);
            E *= m;
            m *= q2;
        }
    }

    // loss contribution = sum((1-E)*p) = tsp - tsep
    float tot = tsp - tsep;
    #pragma unroll
    for (int o = 16; o > 0; o >>= 1)
        tot += __shfl_xor_sync(0xFFFFFFFFu, tot, o);

    __shared__ double wsum[8];
    if (lane == 0) wsum[wid] = (double)tot;
    __syncthreads();

    if (threadIdx.x == 0) {
        double s = 0.0;
        #pragma unroll
        for (int k = 0; k < 8; k++) s += wsum[k];
        g_block[blockIdx.x] = s;
    }
}

// ---------------------------------------------------------------------------
// Kernel 2: single block. Sums the NBLK partials and the active-area
// normalizer (sum tl*ml) on-device; writes the final scalar.
// ---------------------------------------------------------------------------
__global__ __launch_bounds__(1024) void final_kernel(
    const int* __restrict__ tlen,
    const int* __restrict__ mlen,
    float* __restrict__ out)
{
    const int i = threadIdx.x;
    double v = 0.0;
    for (int k = i; k < NBLK; k += 1024) v += g_block[k];
    double a = (i < BATCH) ? (double)tlen[i] * (double)mlen[i] : 0.0;

    #pragma unroll
    for (int o = 16; o > 0; o >>= 1) {
        v += __shfl_xor_sync(0xFFFFFFFFu, v, o);
        a += __shfl_xor_sync(0xFFFFFFFFu, a, o);
    }

    __shared__ double sv[32], sa[32];
    const int lane = i & 31;
    const int wid  = i >> 5;
    if (lane == 0) { sv[wid] = v; sa[wid] = a; }
    __syncthreads();

    if (i < 32) {
        v = sv[i];
        a = sa[i];
        #pragma unroll
        for (int o = 16; o > 0; o >>= 1) {
            v += __shfl_xor_sync(0xFFFFFFFFu, v, o);
            a += __shfl_xor_sync(0xFFFFFFFFu, a, o);
        }
        if (i == 0)
            out[0] = (float)(v / a);   // attention_weight = 1.0
    }
}

// ---------------------------------------------------------------------------
// Inputs (metadata order): targets (unused), predictions, text_lengths,
// mel_lengths. Output: single float.
// ---------------------------------------------------------------------------
extern "C" void kernel_launch(void* const* d_in, const int* in_sizes, int n_in,
                              void* d_out, int out_size)
{
    (void)in_sizes; (void)n_in; (void)out_size;
    const float* pred = (const float*)d_in[1];
    const int*   tlen = (const int*)d_in[2];
    const int*   mlen = (const int*)d_in[3];
    float*       out  = (float*)d_out;

    row_kernel<<<NBLK, NTHR>>>(pred, tlen, mlen);
    final_kernel<<<1, 1024>>>(tlen, mlen, out);
}